// round 1
// baseline (speedup 1.0000x reference)
#include <cuda_runtime.h>
#include <math.h>

#define BATCH 2
#define NQL   4096
#define NKV   4096
#define HID   256
#define NH    4
#define DH    64
#define MTOT  (BATCH * NQL)   // 8192 rows for every GEMM

// ---------------- scratch (device globals; no allocation allowed) ----------
__device__ float g_Q[BATCH * NH * NQL * DH];   // [b][h][q][d], pre-scaled by 1/sqrt(DH)
__device__ float g_K[BATCH * NH * NKV * DH];   // [b][h][k][d]
__device__ float g_V[BATCH * NH * NKV * DH];   // [b][h][k][d]
__device__ float g_AO[BATCH * NQL * HID];      // attention output, row-major [b*NQ+q][hid]

// ---------------------------------------------------------------------------
// Tiled fp32 GEMM: C[M=8192, N=256] = A[8192,256] @ W[256,256]; then
// (acc + bias[n]) * alpha. scatter=0: C row-major. scatter=1: write to
// per-(b,h) layout [b][h][row][d] (used for Q/K/V).
// Block tile 64x64, BK=32, 256 threads, 4x4 micro-tile, float4 smem reads.
// ---------------------------------------------------------------------------
__global__ __launch_bounds__(256) void gemm_bias_kernel(
    const float* __restrict__ A, const float* __restrict__ W,
    const float* __restrict__ bias, float* __restrict__ C,
    float alpha, int scatter)
{
    __shared__ float As[32 * 68];   // [k][m], stride 68 (pad kills conflicts)
    __shared__ float Ws[32 * 64];   // [k][n]

    const int t  = threadIdx.x;
    const int tx = t & 15;          // -> 4 output cols 4*tx..
    const int ty = t >> 4;          // -> 4 output rows 4*ty..
    const int m0 = blockIdx.y * 64;
    const int n0 = blockIdx.x * 64;

    float acc[4][4] = {};

    for (int k0 = 0; k0 < HID; k0 += 32) {
        // cooperative load: A tile (64x32, transposed into As) + W tile (32x64)
#pragma unroll
        for (int l = 0; l < 2; ++l) {
            int idx = t + 256 * l;            // 0..511
            int row = idx >> 3, kq = idx & 7; // A: 8 float4 per row
            float4 av = *(const float4*)(A + (size_t)(m0 + row) * HID + k0 + 4 * kq);
            As[(4 * kq + 0) * 68 + row] = av.x;
            As[(4 * kq + 1) * 68 + row] = av.y;
            As[(4 * kq + 2) * 68 + row] = av.z;
            As[(4 * kq + 3) * 68 + row] = av.w;
            int kk = idx >> 4, nq = idx & 15; // W: 16 float4 per row
            *(float4*)(Ws + kk * 64 + 4 * nq) =
                *(const float4*)(W + (size_t)(k0 + kk) * HID + n0 + 4 * nq);
        }
        __syncthreads();

#pragma unroll
        for (int k = 0; k < 32; ++k) {
            float4 a = *(const float4*)(As + k * 68 + 4 * ty);
            float4 b = *(const float4*)(Ws + k * 64 + 4 * tx);
            acc[0][0] += a.x * b.x; acc[0][1] += a.x * b.y; acc[0][2] += a.x * b.z; acc[0][3] += a.x * b.w;
            acc[1][0] += a.y * b.x; acc[1][1] += a.y * b.y; acc[1][2] += a.y * b.z; acc[1][3] += a.y * b.w;
            acc[2][0] += a.z * b.x; acc[2][1] += a.z * b.y; acc[2][2] += a.z * b.z; acc[2][3] += a.z * b.w;
            acc[3][0] += a.w * b.x; acc[3][1] += a.w * b.y; acc[3][2] += a.w * b.z; acc[3][3] += a.w * b.w;
        }
        __syncthreads();
    }

    float4 bv = *(const float4*)(bias + n0 + 4 * tx);
#pragma unroll
    for (int i = 0; i < 4; ++i) {
        float4 o;
        o.x = (acc[i][0] + bv.x) * alpha;
        o.y = (acc[i][1] + bv.y) * alpha;
        o.z = (acc[i][2] + bv.z) * alpha;
        o.w = (acc[i][3] + bv.w) * alpha;
        int m = m0 + 4 * ty + i;
        if (!scatter) {
            *(float4*)(C + (size_t)m * HID + n0 + 4 * tx) = o;
        } else {
            int b  = m >> 12;        // / NQL
            int rq = m & 4095;       // % NQL
            int h  = n0 >> 6;        // BN==DH -> one head per block column
            *(float4*)(C + (((size_t)(b * NH + h) * NQL) + rq) * DH + 4 * tx) = o;
        }
    }
}

// ---------------------------------------------------------------------------
// Flash attention, fp32. One CTA = 64 q rows of one (b,h). Streams KV in
// 64-row tiles. 256 threads, 4x4 micro-tiles for both S=QK^T and O+=P@V.
// Row softmax stats reduced over the 16 threads that share a row (shfl_xor).
// Q is pre-scaled by 1/sqrt(DH). Mask enters as additive bias (0 / -inf).
// ---------------------------------------------------------------------------
__global__ __launch_bounds__(256) void attn_kernel(const int* __restrict__ kv_mask)
{
    extern __shared__ float sm[];
    float* Qs = sm;                 // [64][68]
    float* Ks = Qs + 64 * 68;       // [64][68]
    float* Vs = Ks + 64 * 68;       // [64][68]
    float* Ps = Vs + 64 * 68;       // [64][68]
    float* mb = Ps + 64 * 68;       // [64] additive mask bias

    const int t  = threadIdx.x;
    const int tx = t & 15;          // 4 cols 4*tx..
    const int ty = t >> 4;          // 4 rows 4*ty..
    const int q0 = blockIdx.x * 64;
    const int bh = blockIdx.y;      // b*NH + h
    const int b  = bh >> 2;

    const float* Qg = g_Q + ((size_t)bh * NQL + q0) * DH;
    const float* Kg = g_K + (size_t)bh * NKV * DH;
    const float* Vg = g_V + (size_t)bh * NKV * DH;

    // load Q tile (64x64)
#pragma unroll
    for (int l = 0; l < 4; ++l) {
        int idx = t + 256 * l;                 // 0..1023
        int row = idx >> 4, dq = idx & 15;
        *(float4*)(Qs + row * 68 + 4 * dq) =
            *(const float4*)(Qg + (size_t)row * DH + 4 * dq);
    }

    float m_i[4], l_i[4], acc[4][4] = {};
#pragma unroll
    for (int i = 0; i < 4; ++i) { m_i[i] = -1e30f; l_i[i] = 0.0f; }

    for (int kt = 0; kt < NKV / 64; ++kt) {
        const int k0 = kt * 64;
        // load K, V tiles (+ mask bias)
#pragma unroll
        for (int l = 0; l < 4; ++l) {
            int idx = t + 256 * l;
            int row = idx >> 4, dq = idx & 15;
            *(float4*)(Ks + row * 68 + 4 * dq) =
                *(const float4*)(Kg + (size_t)(k0 + row) * DH + 4 * dq);
            *(float4*)(Vs + row * 68 + 4 * dq) =
                *(const float4*)(Vg + (size_t)(k0 + row) * DH + 4 * dq);
        }
        if (t < 64) mb[t] = kv_mask[b * NKV + k0 + t] ? 0.0f : -INFINITY;
        __syncthreads();

        // S = Qs @ Ks^T for this thread's 4x4 patch
        float s[4][4] = {};
#pragma unroll
        for (int d0 = 0; d0 < DH; d0 += 4) {
            float4 qv[4], kv[4];
#pragma unroll
            for (int i = 0; i < 4; ++i) qv[i] = *(const float4*)(Qs + (4 * ty + i) * 68 + d0);
#pragma unroll
            for (int j = 0; j < 4; ++j) kv[j] = *(const float4*)(Ks + (4 * tx + j) * 68 + d0);
#pragma unroll
            for (int i = 0; i < 4; ++i)
#pragma unroll
                for (int j = 0; j < 4; ++j)
                    s[i][j] += qv[i].x * kv[j].x + qv[i].y * kv[j].y
                             + qv[i].z * kv[j].z + qv[i].w * kv[j].w;
        }

        float4 mbv = *(const float4*)(mb + 4 * tx);
#pragma unroll
        for (int i = 0; i < 4; ++i) {
            s[i][0] += mbv.x; s[i][1] += mbv.y; s[i][2] += mbv.z; s[i][3] += mbv.w;
        }

        // online softmax per row; write P tile to smem
#pragma unroll
        for (int i = 0; i < 4; ++i) {
            float rmax = fmaxf(fmaxf(s[i][0], s[i][1]), fmaxf(s[i][2], s[i][3]));
#pragma unroll
            for (int off = 8; off >= 1; off >>= 1)
                rmax = fmaxf(rmax, __shfl_xor_sync(0xffffffffu, rmax, off));
            float mnew = fmaxf(m_i[i], rmax);
            float corr = __expf(m_i[i] - mnew);
            m_i[i] = mnew;
            float p0 = __expf(s[i][0] - mnew);
            float p1 = __expf(s[i][1] - mnew);
            float p2 = __expf(s[i][2] - mnew);
            float p3 = __expf(s[i][3] - mnew);
            float rsum = p0 + p1 + p2 + p3;
#pragma unroll
            for (int off = 8; off >= 1; off >>= 1)
                rsum += __shfl_xor_sync(0xffffffffu, rsum, off);
            l_i[i] = l_i[i] * corr + rsum;
            acc[i][0] *= corr; acc[i][1] *= corr; acc[i][2] *= corr; acc[i][3] *= corr;
            *(float4*)(Ps + (4 * ty + i) * 68 + 4 * tx) = make_float4(p0, p1, p2, p3);
        }
        __syncthreads();

        // O += P @ V
#pragma unroll
        for (int c0 = 0; c0 < 64; c0 += 4) {
            float4 pv[4], vv[4];
#pragma unroll
            for (int i = 0; i < 4; ++i) pv[i] = *(const float4*)(Ps + (4 * ty + i) * 68 + c0);
#pragma unroll
            for (int c = 0; c < 4; ++c) vv[c] = *(const float4*)(Vs + (c0 + c) * 68 + 4 * tx);
#pragma unroll
            for (int i = 0; i < 4; ++i) {
                acc[i][0] += pv[i].x * vv[0].x + pv[i].y * vv[1].x + pv[i].z * vv[2].x + pv[i].w * vv[3].x;
                acc[i][1] += pv[i].x * vv[0].y + pv[i].y * vv[1].y + pv[i].z * vv[2].y + pv[i].w * vv[3].y;
                acc[i][2] += pv[i].x * vv[0].z + pv[i].y * vv[1].z + pv[i].z * vv[2].z + pv[i].w * vv[3].z;
                acc[i][3] += pv[i].x * vv[0].w + pv[i].y * vv[1].w + pv[i].z * vv[2].w + pv[i].w * vv[3].w;
            }
        }
        __syncthreads();
    }

    // epilogue: normalize and write to [b][q][h*DH + d] row-major buffer
    const int h = bh & 3;
#pragma unroll
    for (int i = 0; i < 4; ++i) {
        float inv = 1.0f / l_i[i];
        float4 o = make_float4(acc[i][0] * inv, acc[i][1] * inv,
                               acc[i][2] * inv, acc[i][3] * inv);
        size_t off = ((size_t)b * NQL + q0 + 4 * ty + i) * HID + h * DH + 4 * tx;
        *(float4*)(g_AO + off) = o;
    }
}

// ---------------------------------------------------------------------------
extern "C" void kernel_launch(void* const* d_in, const int* in_sizes, int n_in,
                              void* d_out, int out_size)
{
    const float* query     = (const float*)d_in[0];
    const float* key_value = (const float*)d_in[1];
    const int*   kv_mask   = (const int*)  d_in[2];
    const float* Wq = (const float*)d_in[3];
    const float* bq = (const float*)d_in[4];
    const float* Wk = (const float*)d_in[5];
    const float* bk = (const float*)d_in[6];
    const float* Wv = (const float*)d_in[7];
    const float* bv = (const float*)d_in[8];
    const float* Wo = (const float*)d_in[9];
    const float* bo = (const float*)d_in[10];
    float* out = (float*)d_out;

    float *Qp, *Kp, *Vp, *AOp;
    cudaGetSymbolAddress((void**)&Qp,  g_Q);
    cudaGetSymbolAddress((void**)&Kp,  g_K);
    cudaGetSymbolAddress((void**)&Vp,  g_V);
    cudaGetSymbolAddress((void**)&AOp, g_AO);

    dim3 gblk(256);
    dim3 ggrid(HID / 64, MTOT / 64);   // (4, 128)

    const float inv_scale = 0.125f;    // 1/sqrt(DH)
    gemm_bias_kernel<<<ggrid, gblk>>>(query,     Wq, bq, Qp, inv_scale, 1);
    gemm_bias_kernel<<<ggrid, gblk>>>(key_value, Wk, bk, Kp, 1.0f,      1);
    gemm_bias_kernel<<<ggrid, gblk>>>(key_value, Wv, bv, Vp, 1.0f,      1);

    size_t smem = (size_t)(4 * 64 * 68 + 64) * sizeof(float);   // ~68.3 KB
    cudaFuncSetAttribute(attn_kernel, cudaFuncAttributeMaxDynamicSharedMemorySize, (int)smem);
    attn_kernel<<<dim3(NQL / 64, BATCH * NH), 256, smem>>>(kv_mask);

    gemm_bias_kernel<<<ggrid, gblk>>>(AOp, Wo, bo, out, 1.0f, 0);
}

// round 4
// speedup vs baseline: 5.3491x; 5.3491x over previous
#include <cuda_runtime.h>
#include <cuda_fp16.h>
#include <math.h>
#include <stdint.h>

#define BATCH 2
#define NQL   4096
#define NKVL  4096
#define HID   256
#define NH    4
#define DH    64
#define MTOT  (BATCH * NQL)

// ---------------- scratch (device globals) ---------------------------------
__device__ __align__(16) __half g_Qh[BATCH * NH * NQL * DH];   // [bh][q][d], pre-scaled
__device__ __align__(16) __half g_Kh[BATCH * NH * NKVL * DH];  // [bh][kv][d]
__device__ __align__(16) __half g_Vh[BATCH * NH * NKVL * DH];  // [bh][kv][d]
__device__ float g_AO[BATCH * NQL * HID];                      // attn out fp32

// ---------------- PTX helpers ----------------------------------------------
__device__ __forceinline__ uint32_t smem_u32(const void* p) {
    uint32_t a;
    asm("{ .reg .u64 t; cvta.to.shared.u64 t, %1; cvt.u32.u64 %0, t; }" : "=r"(a) : "l"(p));
    return a;
}
__device__ __forceinline__ void ldsm4(uint32_t& r0, uint32_t& r1, uint32_t& r2, uint32_t& r3, uint32_t a) {
    asm volatile("ldmatrix.sync.aligned.m8n8.x4.shared.b16 {%0,%1,%2,%3}, [%4];"
                 : "=r"(r0), "=r"(r1), "=r"(r2), "=r"(r3) : "r"(a));
}
__device__ __forceinline__ void ldsm4t(uint32_t& r0, uint32_t& r1, uint32_t& r2, uint32_t& r3, uint32_t a) {
    asm volatile("ldmatrix.sync.aligned.m8n8.x4.trans.shared.b16 {%0,%1,%2,%3}, [%4];"
                 : "=r"(r0), "=r"(r1), "=r"(r2), "=r"(r3) : "r"(a));
}
__device__ __forceinline__ void mma16816(float* c, const uint32_t* a, uint32_t b0, uint32_t b1) {
    asm volatile("mma.sync.aligned.m16n8k16.row.col.f32.f16.f16.f32 "
        "{%0,%1,%2,%3}, {%4,%5,%6,%7}, {%8,%9}, {%0,%1,%2,%3};"
        : "+f"(c[0]), "+f"(c[1]), "+f"(c[2]), "+f"(c[3])
        : "r"(a[0]), "r"(a[1]), "r"(a[2]), "r"(a[3]), "r"(b0), "r"(b1));
}
__device__ __forceinline__ uint32_t packh2(float x, float y) {
    __half2 h = __floats2half2_rn(x, y);
    return *(uint32_t*)&h;
}

// ---------------------------------------------------------------------------
// Projection GEMM: C = A[8192,256] @ W[256,256] + bias, times alpha.
// mode 0: fp32 row-major; mode 1: fp16 scatter to [bh][row][d]
// ---------------------------------------------------------------------------
__global__ __launch_bounds__(256) void gemm_bias_kernel(
    const float* __restrict__ A, const float* __restrict__ W,
    const float* __restrict__ bias, void* __restrict__ Cv,
    float alpha, int mode)
{
    __shared__ float As[32 * 68];
    __shared__ float Ws[32 * 64];

    const int t  = threadIdx.x;
    const int tx = t & 15;
    const int ty = t >> 4;
    const int m0 = blockIdx.y * 64;
    const int n0 = blockIdx.x * 64;

    float acc[4][4] = {};

    for (int k0 = 0; k0 < HID; k0 += 32) {
#pragma unroll
        for (int l = 0; l < 2; ++l) {
            int idx = t + 256 * l;
            int row = idx >> 3, kq = idx & 7;
            float4 av = *(const float4*)(A + (size_t)(m0 + row) * HID + k0 + 4 * kq);
            As[(4 * kq + 0) * 68 + row] = av.x;
            As[(4 * kq + 1) * 68 + row] = av.y;
            As[(4 * kq + 2) * 68 + row] = av.z;
            As[(4 * kq + 3) * 68 + row] = av.w;
            int kk = idx >> 4, nq = idx & 15;
            *(float4*)(Ws + kk * 64 + 4 * nq) =
                *(const float4*)(W + (size_t)(k0 + kk) * HID + n0 + 4 * nq);
        }
        __syncthreads();
#pragma unroll
        for (int k = 0; k < 32; ++k) {
            float4 a = *(const float4*)(As + k * 68 + 4 * ty);
            float4 b = *(const float4*)(Ws + k * 64 + 4 * tx);
            acc[0][0] += a.x * b.x; acc[0][1] += a.x * b.y; acc[0][2] += a.x * b.z; acc[0][3] += a.x * b.w;
            acc[1][0] += a.y * b.x; acc[1][1] += a.y * b.y; acc[1][2] += a.y * b.z; acc[1][3] += a.y * b.w;
            acc[2][0] += a.z * b.x; acc[2][1] += a.z * b.y; acc[2][2] += a.z * b.z; acc[2][3] += a.z * b.w;
            acc[3][0] += a.w * b.x; acc[3][1] += a.w * b.y; acc[3][2] += a.w * b.z; acc[3][3] += a.w * b.w;
        }
        __syncthreads();
    }

    float4 bv = *(const float4*)(bias + n0 + 4 * tx);
#pragma unroll
    for (int i = 0; i < 4; ++i) {
        float4 o;
        o.x = (acc[i][0] + bv.x) * alpha;
        o.y = (acc[i][1] + bv.y) * alpha;
        o.z = (acc[i][2] + bv.z) * alpha;
        o.w = (acc[i][3] + bv.w) * alpha;
        int m = m0 + 4 * ty + i;
        if (mode == 0) {
            float* C = (float*)Cv;
            *(float4*)(C + (size_t)m * HID + n0 + 4 * tx) = o;
        } else {
            __half* C = (__half*)Cv;
            int b  = m >> 12;
            int rq = m & 4095;
            int h  = n0 >> 6;       // 64-wide block column == one head
            __half2* p = (__half2*)(C + (((size_t)(b * NH + h) * NQL) + rq) * DH + 4 * tx);
            p[0] = __floats2half2_rn(o.x, o.y);
            p[1] = __floats2half2_rn(o.z, o.w);
        }
    }
}

// ---------------------------------------------------------------------------
// HMMA flash attention (no-max softmax). CTA = 64 q rows of one (b,h),
// 4 warps x 16 rows. KV streamed in 64-row tiles, double-buffered.
// ---------------------------------------------------------------------------
#define BM 64
#define BN 64
#define KST 72   // half stride (144 B): conflict-free for ldmatrix & STS

__global__ __launch_bounds__(128) void attn_hmma_kernel(const int* __restrict__ kv_mask)
{
    __shared__ __half sQ[BM * KST];
    __shared__ __half sK[2][BN * KST];
    __shared__ __half sV[2][BN * KST];
    __shared__ float  smask[2][BN];

    const int tid  = threadIdx.x;
    const int warp = tid >> 5;
    const int lane = tid & 31;
    const int g    = lane >> 2;       // group (row within 8)
    const int tig  = lane & 3;
    const int q0   = blockIdx.x * BM;
    const int bh   = blockIdx.y;
    const int b    = bh >> 2, h = bh & 3;
    const int m0   = warp * 16;

    const __half* Qg = g_Qh + ((size_t)bh * NQL + q0) * DH;
    const __half* Kg = g_Kh + (size_t)bh * NKVL * DH;
    const __half* Vg = g_Vh + (size_t)bh * NKVL * DH;
    const int*    Mg = kv_mask + b * NKVL;

    // ---- stage Q tile + KV tile 0 ----
#pragma unroll
    for (int l = 0; l < 4; ++l) {
        int idx = tid + 128 * l;          // 512 chunks of 16B
        int row = idx >> 3, c = idx & 7;
        *(uint4*)(sQ + row * KST + c * 8)    = *(const uint4*)(Qg + (size_t)row * DH + c * 8);
        *(uint4*)(sK[0] + row * KST + c * 8) = *(const uint4*)(Kg + (size_t)row * DH + c * 8);
        *(uint4*)(sV[0] + row * KST + c * 8) = *(const uint4*)(Vg + (size_t)row * DH + c * 8);
    }
    if (tid < BN) smask[0][tid] = Mg[tid] ? 1.0f : 0.0f;
    __syncthreads();

    // ---- Q fragments (held for whole kernel) ----
    // ldmatrix x4 at (m0, 16*kc): row = m0 + (lane&7) + ((lane>>3)&1)*8, col = k0 + (lane>>4)*8
    uint32_t qa[4][4];
    {
        int r = (lane & 7) + ((lane >> 3) & 1) * 8;
        int cq = (lane >> 4) * 8;
#pragma unroll
        for (int kc = 0; kc < 4; ++kc) {
            uint32_t a = smem_u32(sQ + (m0 + r) * KST + kc * 16 + cq);
            ldsm4(qa[kc][0], qa[kc][1], qa[kc][2], qa[kc][3], a);
        }
    }

    float oc[8][4];
#pragma unroll
    for (int i = 0; i < 8; ++i)
#pragma unroll
        for (int j = 0; j < 4; ++j) oc[i][j] = 0.0f;
    float lsum0 = 0.0f, lsum1 = 0.0f;

    // ldmatrix lane address components
    const int krow = (lane & 7) + ((lane >> 4) << 3);        // K b-frags: n-offset
    const int kcol = ((lane >> 3) & 1) << 3;                 // K b-frags: k-offset
    const int vrow = (lane & 7) + (((lane >> 3) & 1) << 3);  // V b-frags: k-offset
    const int vcol = (lane >> 4) << 3;                       // V b-frags: n-offset

    const int NT = NKVL / BN;   // 64

    for (int t = 0; t < NT; ++t) {
        const int buf = t & 1;
        const __half* s_k = sK[buf];
        const __half* s_v = sV[buf];

        // prefetch tile t+1 into registers
        uint4 pk[4], pv[4];
        float mnext = 1.0f;
        if (t + 1 < NT) {
            const __half* Kn = Kg + (size_t)(t + 1) * BN * DH;
            const __half* Vn = Vg + (size_t)(t + 1) * BN * DH;
#pragma unroll
            for (int l = 0; l < 4; ++l) {
                int idx = tid + 128 * l;
                int row = idx >> 3, c = idx & 7;
                pk[l] = *(const uint4*)(Kn + (size_t)row * DH + c * 8);
                pv[l] = *(const uint4*)(Vn + (size_t)row * DH + c * 8);
            }
            if (tid < BN) mnext = Mg[(t + 1) * BN + tid] ? 1.0f : 0.0f;
        }

        // ---- per 16-kv chunk: S -> softmax -> PV ----
#pragma unroll
        for (int np = 0; np < 4; ++np) {
            const int n0 = 16 * np;
            float s0[4] = {0, 0, 0, 0};   // ntile n0
            float s1[4] = {0, 0, 0, 0};   // ntile n0+8
#pragma unroll
            for (int kc = 0; kc < 4; ++kc) {
                uint32_t b0, b1, b2, b3;
                uint32_t a = smem_u32(s_k + (n0 + krow) * KST + kc * 16 + kcol);
                ldsm4(b0, b1, b2, b3, a);
                mma16816(s0, qa[kc], b0, b1);
                mma16816(s1, qa[kc], b2, b3);
            }
            // masks for this chunk's columns
            float mA0 = smask[buf][n0 + 2 * tig];
            float mA1 = smask[buf][n0 + 2 * tig + 1];
            float mB0 = smask[buf][n0 + 8 + 2 * tig];
            float mB1 = smask[buf][n0 + 8 + 2 * tig + 1];

            float p00 = __expf(s0[0]) * mA0, p01 = __expf(s0[1]) * mA1;
            float p02 = __expf(s0[2]) * mA0, p03 = __expf(s0[3]) * mA1;
            float p10 = __expf(s1[0]) * mB0, p11 = __expf(s1[1]) * mB1;
            float p12 = __expf(s1[2]) * mB0, p13 = __expf(s1[3]) * mB1;

            lsum0 += (p00 + p01) + (p10 + p11);
            lsum1 += (p02 + p03) + (p12 + p13);

            uint32_t pa[4];
            pa[0] = packh2(p00, p01);     // row g,   k 0-7 of chunk
            pa[1] = packh2(p02, p03);     // row g+8, k 0-7
            pa[2] = packh2(p10, p11);     // row g,   k 8-15
            pa[3] = packh2(p12, p13);     // row g+8, k 8-15

#pragma unroll
            for (int dp = 0; dp < 4; ++dp) {
                uint32_t b0, b1, b2, b3;
                uint32_t a = smem_u32(s_v + (n0 + vrow) * KST + dp * 16 + vcol);
                ldsm4t(b0, b1, b2, b3, a);
                mma16816(oc[2 * dp],     pa, b0, b1);
                mma16816(oc[2 * dp + 1], pa, b2, b3);
            }
        }

        __syncthreads();   // done reading buf; (other buffer free since t-1 barrier)
        if (t + 1 < NT) {
            __half* dK = sK[1 - buf];
            __half* dV = sV[1 - buf];
#pragma unroll
            for (int l = 0; l < 4; ++l) {
                int idx = tid + 128 * l;
                int row = idx >> 3, c = idx & 7;
                *(uint4*)(dK + row * KST + c * 8) = pk[l];
                *(uint4*)(dV + row * KST + c * 8) = pv[l];
            }
            if (tid < BN) smask[1 - buf][tid] = mnext;
            __syncthreads();
        }
    }

    // ---- quad-reduce row sums, normalize, store ----
    lsum0 += __shfl_xor_sync(0xffffffffu, lsum0, 1);
    lsum0 += __shfl_xor_sync(0xffffffffu, lsum0, 2);
    lsum1 += __shfl_xor_sync(0xffffffffu, lsum1, 1);
    lsum1 += __shfl_xor_sync(0xffffffffu, lsum1, 2);
    float inv0 = (lsum0 > 0.0f) ? 1.0f / lsum0 : 0.0f;
    float inv1 = (lsum1 > 0.0f) ? 1.0f / lsum1 : 0.0f;

    const size_t row0 = (size_t)(b * NQL) + q0 + m0 + g;
#pragma unroll
    for (int dt = 0; dt < 8; ++dt) {
        int col = h * DH + 8 * dt + 2 * tig;
        *(float2*)(g_AO + row0 * HID + col) =
            make_float2(oc[dt][0] * inv0, oc[dt][1] * inv0);
        *(float2*)(g_AO + (row0 + 8) * HID + col) =
            make_float2(oc[dt][2] * inv1, oc[dt][3] * inv1);
    }
}

// ---------------------------------------------------------------------------
extern "C" void kernel_launch(void* const* d_in, const int* in_sizes, int n_in,
                              void* d_out, int out_size)
{
    const float* query     = (const float*)d_in[0];
    const float* key_value = (const float*)d_in[1];
    const int*   kv_mask   = (const int*)  d_in[2];
    const float* Wq = (const float*)d_in[3];
    const float* bq = (const float*)d_in[4];
    const float* Wk = (const float*)d_in[5];
    const float* bk = (const float*)d_in[6];
    const float* Wv = (const float*)d_in[7];
    const float* bv = (const float*)d_in[8];
    const float* Wo = (const float*)d_in[9];
    const float* bo = (const float*)d_in[10];

    void *Qp, *Kp, *Vp, *AOp;
    cudaGetSymbolAddress(&Qp,  g_Qh);
    cudaGetSymbolAddress(&Kp,  g_Kh);
    cudaGetSymbolAddress(&Vp,  g_Vh);
    cudaGetSymbolAddress(&AOp, g_AO);

    dim3 gblk(256);
    dim3 ggrid(HID / 64, MTOT / 64);   // (4, 128)

    gemm_bias_kernel<<<ggrid, gblk>>>(query,     Wq, bq, Qp, 0.125f, 1);  // Q pre-scaled
    gemm_bias_kernel<<<ggrid, gblk>>>(key_value, Wk, bk, Kp, 1.0f,   1);  // K
    gemm_bias_kernel<<<ggrid, gblk>>>(key_value, Wv, bv, Vp, 1.0f,   1);  // V

    attn_hmma_kernel<<<dim3(NQL / BM, BATCH * NH), 128>>>(kv_mask);

    gemm_bias_kernel<<<ggrid, gblk>>>((const float*)AOp, Wo, bo, d_out, 1.0f, 0);
}

// round 8
// speedup vs baseline: 8.6828x; 1.6232x over previous
#include <cuda_runtime.h>
#include <cuda_fp16.h>
#include <math.h>
#include <stdint.h>

#define BATCH 2
#define NQL   4096
#define NKVL  4096
#define HID   256
#define NH    4
#define DH    64
#define MTOT  (BATCH * NQL)

// ---------------- scratch (device globals) ---------------------------------
__device__ __align__(16) __half g_Qh[BATCH * NH * NQL * DH];   // [bh][q][d], pre-scaled
__device__ __align__(16) __half g_Kh[BATCH * NH * NKVL * DH];  // [bh][kv][d]
__device__ __align__(16) __half g_Vh[BATCH * NH * NKVL * DH];  // [bh][kv][d]
__device__ float g_AO[BATCH * NQL * HID];                      // attn out fp32

// ---------------- PTX helpers ----------------------------------------------
__device__ __forceinline__ uint32_t smem_u32(const void* p) {
    uint32_t a;
    asm("{ .reg .u64 t; cvta.to.shared.u64 t, %1; cvt.u32.u64 %0, t; }" : "=r"(a) : "l"(p));
    return a;
}
__device__ __forceinline__ void ldsm4(uint32_t& r0, uint32_t& r1, uint32_t& r2, uint32_t& r3, uint32_t a) {
    asm volatile("ldmatrix.sync.aligned.m8n8.x4.shared.b16 {%0,%1,%2,%3}, [%4];"
                 : "=r"(r0), "=r"(r1), "=r"(r2), "=r"(r3) : "r"(a));
}
__device__ __forceinline__ void ldsm4t(uint32_t& r0, uint32_t& r1, uint32_t& r2, uint32_t& r3, uint32_t a) {
    asm volatile("ldmatrix.sync.aligned.m8n8.x4.trans.shared.b16 {%0,%1,%2,%3}, [%4];"
                 : "=r"(r0), "=r"(r1), "=r"(r2), "=r"(r3) : "r"(a));
}
__device__ __forceinline__ void mma16816(float* c, const uint32_t* a, uint32_t b0, uint32_t b1) {
    asm volatile("mma.sync.aligned.m16n8k16.row.col.f32.f16.f16.f32 "
        "{%0,%1,%2,%3}, {%4,%5,%6,%7}, {%8,%9}, {%0,%1,%2,%3};"
        : "+f"(c[0]), "+f"(c[1]), "+f"(c[2]), "+f"(c[3])
        : "r"(a[0]), "r"(a[1]), "r"(a[2]), "r"(a[3]), "r"(b0), "r"(b1));
}
__device__ __forceinline__ uint32_t packh2(float x, float y) {
    __half2 h = __floats2half2_rn(x, y);
    return *(uint32_t*)&h;
}
#define CP16(dst, src)  asm volatile("cp.async.cg.shared.global [%0], [%1], 16;" :: "r"(dst), "l"(src))
#define CP_COMMIT()     asm volatile("cp.async.commit_group;" ::: "memory")
#define CP_WAIT0()      asm volatile("cp.async.wait_group 0;" ::: "memory")

// ---------------------------------------------------------------------------
// HMMA projection GEMM: C[8192,256] = A(fp32) @ W(fp32) + bias, times alpha.
// CTA tile 64x64, BK=64, 4 warps (16 rows each). fp32 inputs converted to
// fp16 during staging. mode 1: plain fp16 pass, scatter fp16 to [bh][row][d].
// mode 0: Markidis split (hi*hi + lo*hi + hi*lo) -> near-fp32 accuracy,
// fp32 row-major output (final projection).
// ---------------------------------------------------------------------------
#define GST 72

__device__ __forceinline__ void hgemm_pass(const __half* sA, const __half* sW,
                                           float c[8][4], int lane, int m0r)
{
    const int r   = (lane & 7) + ((lane >> 3) & 1) * 8;
    const int cq  = (lane >> 4) * 8;
    const int wr  = (lane & 7) + (((lane >> 3) & 1) << 3);
    const int wc  = (lane >> 4) << 3;

    uint32_t a[4][4];
#pragma unroll
    for (int kc = 0; kc < 4; ++kc) {
        uint32_t ad = smem_u32(sA + (m0r + r) * GST + kc * 16 + cq);
        ldsm4(a[kc][0], a[kc][1], a[kc][2], a[kc][3], ad);
    }
#pragma unroll
    for (int dp = 0; dp < 4; ++dp) {
#pragma unroll
        for (int kc = 0; kc < 4; ++kc) {
            uint32_t b0, b1, b2, b3;
            uint32_t ad = smem_u32(sW + (kc * 16 + wr) * GST + dp * 16 + wc);
            ldsm4t(b0, b1, b2, b3, ad);
            mma16816(c[2 * dp],     a[kc], b0, b1);
            mma16816(c[2 * dp + 1], a[kc], b2, b3);
        }
    }
}

__global__ __launch_bounds__(128) void hgemm_kernel(
    const float* __restrict__ A, const float* __restrict__ W,
    const float* __restrict__ bias, void* __restrict__ Cv,
    float alpha, int mode)
{
    __shared__ __half sA[64 * GST];
    __shared__ __half sW[64 * GST];
    __shared__ __half sAlo[64 * GST];
    __shared__ __half sWlo[64 * GST];

    const int tid  = threadIdx.x;
    const int warp = tid >> 5;
    const int lane = tid & 31;
    const int m0   = blockIdx.y * 64;
    const int n0   = blockIdx.x * 64;

    float c[8][4];
#pragma unroll
    for (int i = 0; i < 8; ++i)
#pragma unroll
        for (int j = 0; j < 4; ++j) c[i][j] = 0.0f;

    for (int k0 = 0; k0 < HID; k0 += 64) {
#pragma unroll
        for (int l = 0; l < 4; ++l) {
            int idx = tid + 128 * l;          // 512 chunks of 8 halves
            int row = idx >> 3, cq = idx & 7;
            {
                const float* ga = A + (size_t)(m0 + row) * HID + k0 + cq * 8;
                float4 x0 = *(const float4*)(ga);
                float4 x1 = *(const float4*)(ga + 4);
                __half2 h0 = __floats2half2_rn(x0.x, x0.y);
                __half2 h1 = __floats2half2_rn(x0.z, x0.w);
                __half2 h2 = __floats2half2_rn(x1.x, x1.y);
                __half2 h3 = __floats2half2_rn(x1.z, x1.w);
                *(uint4*)(sA + row * GST + cq * 8) =
                    make_uint4(*(uint32_t*)&h0, *(uint32_t*)&h1, *(uint32_t*)&h2, *(uint32_t*)&h3);
                if (mode == 0) {
                    __half2 l0 = __floats2half2_rn(x0.x - __low2float(h0),  x0.y - __high2float(h0));
                    __half2 l1 = __floats2half2_rn(x0.z - __low2float(h1),  x0.w - __high2float(h1));
                    __half2 l2 = __floats2half2_rn(x1.x - __low2float(h2),  x1.y - __high2float(h2));
                    __half2 l3 = __floats2half2_rn(x1.z - __low2float(h3),  x1.w - __high2float(h3));
                    *(uint4*)(sAlo + row * GST + cq * 8) =
                        make_uint4(*(uint32_t*)&l0, *(uint32_t*)&l1, *(uint32_t*)&l2, *(uint32_t*)&l3);
                }
            }
            {
                const float* gw = W + (size_t)(k0 + row) * HID + n0 + cq * 8;
                float4 x0 = *(const float4*)(gw);
                float4 x1 = *(const float4*)(gw + 4);
                __half2 h0 = __floats2half2_rn(x0.x, x0.y);
                __half2 h1 = __floats2half2_rn(x0.z, x0.w);
                __half2 h2 = __floats2half2_rn(x1.x, x1.y);
                __half2 h3 = __floats2half2_rn(x1.z, x1.w);
                *(uint4*)(sW + row * GST + cq * 8) =
                    make_uint4(*(uint32_t*)&h0, *(uint32_t*)&h1, *(uint32_t*)&h2, *(uint32_t*)&h3);
                if (mode == 0) {
                    __half2 l0 = __floats2half2_rn(x0.x - __low2float(h0),  x0.y - __high2float(h0));
                    __half2 l1 = __floats2half2_rn(x0.z - __low2float(h1),  x0.w - __high2float(h1));
                    __half2 l2 = __floats2half2_rn(x1.x - __low2float(h2),  x1.y - __high2float(h2));
                    __half2 l3 = __floats2half2_rn(x1.z - __low2float(h3),  x1.w - __high2float(h3));
                    *(uint4*)(sWlo + row * GST + cq * 8) =
                        make_uint4(*(uint32_t*)&l0, *(uint32_t*)&l1, *(uint32_t*)&l2, *(uint32_t*)&l3);
                }
            }
        }
        __syncthreads();

        hgemm_pass(sA, sW, c, lane, warp * 16);
        if (mode == 0) {
            hgemm_pass(sAlo, sW, c, lane, warp * 16);
            hgemm_pass(sA, sWlo, c, lane, warp * 16);
        }
        __syncthreads();
    }

    // epilogue
    const int g   = lane >> 2;
    const int tig = lane & 3;
    const int row0 = m0 + warp * 16 + g;
#pragma unroll
    for (int dt = 0; dt < 8; ++dt) {
        int col = 8 * dt + 2 * tig;
        float2 bv = *(const float2*)(bias + n0 + col);
        float v00 = (c[dt][0] + bv.x) * alpha;
        float v01 = (c[dt][1] + bv.y) * alpha;
        float v10 = (c[dt][2] + bv.x) * alpha;
        float v11 = (c[dt][3] + bv.y) * alpha;
        if (mode == 0) {
            float* C = (float*)Cv;
            *(float2*)(C + (size_t)row0 * HID + n0 + col)       = make_float2(v00, v01);
            *(float2*)(C + (size_t)(row0 + 8) * HID + n0 + col) = make_float2(v10, v11);
        } else {
            __half* C = (__half*)Cv;
            int h = n0 >> 6;
            {
                int b = row0 >> 12, rq = row0 & 4095;
                *(__half2*)(C + (((size_t)(b * NH + h) * NQL) + rq) * DH + col) =
                    __floats2half2_rn(v00, v01);
            }
            {
                int m1 = row0 + 8;
                int b = m1 >> 12, rq = m1 & 4095;
                *(__half2*)(C + (((size_t)(b * NH + h) * NQL) + rq) * DH + col) =
                    __floats2half2_rn(v10, v11);
            }
        }
    }
}

// ---------------------------------------------------------------------------
// HMMA flash attention (no-max softmax). CTA = 64 q rows of one (b,h),
// 4 warps x 16 rows. KV streamed in 64-row tiles via cp.async double buffer.
// ---------------------------------------------------------------------------
#define BM 64
#define BN 64
#define KST 72

__global__ __launch_bounds__(128, 4) void attn_hmma_kernel(const int* __restrict__ kv_mask)
{
    __shared__ __half sQ[BM * KST];
    __shared__ __half sK[2][BN * KST];
    __shared__ __half sV[2][BN * KST];
    __shared__ float  smask[2][BN];

    const int tid  = threadIdx.x;
    const int warp = tid >> 5;
    const int lane = tid & 31;
    const int g    = lane >> 2;
    const int tig  = lane & 3;
    const int q0   = blockIdx.x * BM;
    const int bh   = blockIdx.y;
    const int b    = bh >> 2, h = bh & 3;
    const int m0   = warp * 16;

    const __half* Qg = g_Qh + ((size_t)bh * NQL + q0) * DH;
    const __half* Kg = g_Kh + (size_t)bh * NKVL * DH;
    const __half* Vg = g_Vh + (size_t)bh * NKVL * DH;
    const int*    Mg = kv_mask + b * NKVL;

    // staging indices: 512 x 16B chunks per tile, 4 per thread
    const int srow = tid >> 1;             // via idx = tid + 128*l -> row=idx>>3
    (void)srow;

    // ---- prologue: Q direct, KV tile 0 async ----
#pragma unroll
    for (int l = 0; l < 4; ++l) {
        int idx = tid + 128 * l;
        int row = idx >> 3, c = idx & 7;
        *(uint4*)(sQ + row * KST + c * 8) = *(const uint4*)(Qg + (size_t)row * DH + c * 8);
        CP16(smem_u32(sK[0] + row * KST + c * 8), (const void*)(Kg + (size_t)row * DH + c * 8));
        CP16(smem_u32(sV[0] + row * KST + c * 8), (const void*)(Vg + (size_t)row * DH + c * 8));
    }
    CP_COMMIT();
    if (tid < BN) smask[0][tid] = Mg[tid] ? 1.0f : 0.0f;
    CP_WAIT0();
    __syncthreads();

    // ---- Q fragments (held for whole kernel) ----
    uint32_t qa[4][4];
    {
        int r = (lane & 7) + ((lane >> 3) & 1) * 8;
        int cq = (lane >> 4) * 8;
#pragma unroll
        for (int kc = 0; kc < 4; ++kc) {
            uint32_t a = smem_u32(sQ + (m0 + r) * KST + kc * 16 + cq);
            ldsm4(qa[kc][0], qa[kc][1], qa[kc][2], qa[kc][3], a);
        }
    }

    float oc[8][4];
#pragma unroll
    for (int i = 0; i < 8; ++i)
#pragma unroll
        for (int j = 0; j < 4; ++j) oc[i][j] = 0.0f;
    float lsum0 = 0.0f, lsum1 = 0.0f;

    const int krow = (lane & 7) + ((lane >> 4) << 3);
    const int kcol = ((lane >> 3) & 1) << 3;
    const int vrow = (lane & 7) + (((lane >> 3) & 1) << 3);
    const int vcol = (lane >> 4) << 3;

    const int NT = NKVL / BN;   // 64

    for (int t = 0; t < NT; ++t) {
        const int buf = t & 1;
        const __half* s_k = sK[buf];
        const __half* s_v = sV[buf];

        float mnext = 1.0f;
        if (t + 1 < NT) {
            const __half* Kn = Kg + (size_t)(t + 1) * BN * DH;
            const __half* Vn = Vg + (size_t)(t + 1) * BN * DH;
            __half* dK = sK[1 - buf];
            __half* dV = sV[1 - buf];
#pragma unroll
            for (int l = 0; l < 4; ++l) {
                int idx = tid + 128 * l;
                int row = idx >> 3, c = idx & 7;
                CP16(smem_u32(dK + row * KST + c * 8), (const void*)(Kn + (size_t)row * DH + c * 8));
                CP16(smem_u32(dV + row * KST + c * 8), (const void*)(Vn + (size_t)row * DH + c * 8));
            }
            CP_COMMIT();
            if (tid < BN) mnext = Mg[(t + 1) * BN + tid] ? 1.0f : 0.0f;
        }

        // ---- per 16-kv chunk: S -> softmax -> PV ----
#pragma unroll
        for (int np = 0; np < 4; ++np) {
            const int n0 = 16 * np;
            float s0[4] = {0, 0, 0, 0};
            float s1[4] = {0, 0, 0, 0};
#pragma unroll
            for (int kc = 0; kc < 4; ++kc) {
                uint32_t b0, b1, b2, b3;
                uint32_t a = smem_u32(s_k + (n0 + krow) * KST + kc * 16 + kcol);
                ldsm4(b0, b1, b2, b3, a);
                mma16816(s0, qa[kc], b0, b1);
                mma16816(s1, qa[kc], b2, b3);
            }
            float mA0 = smask[buf][n0 + 2 * tig];
            float mA1 = smask[buf][n0 + 2 * tig + 1];
            float mB0 = smask[buf][n0 + 8 + 2 * tig];
            float mB1 = smask[buf][n0 + 8 + 2 * tig + 1];

            float p00 = __expf(s0[0]) * mA0, p01 = __expf(s0[1]) * mA1;
            float p02 = __expf(s0[2]) * mA0, p03 = __expf(s0[3]) * mA1;
            float p10 = __expf(s1[0]) * mB0, p11 = __expf(s1[1]) * mB1;
            float p12 = __expf(s1[2]) * mB0, p13 = __expf(s1[3]) * mB1;

            lsum0 += (p00 + p01) + (p10 + p11);
            lsum1 += (p02 + p03) + (p12 + p13);

            uint32_t pa[4];
            pa[0] = packh2(p00, p01);
            pa[1] = packh2(p02, p03);
            pa[2] = packh2(p10, p11);
            pa[3] = packh2(p12, p13);

#pragma unroll
            for (int dp = 0; dp < 4; ++dp) {
                uint32_t b0, b1, b2, b3;
                uint32_t a = smem_u32(s_v + (n0 + vrow) * KST + dp * 16 + vcol);
                ldsm4t(b0, b1, b2, b3, a);
                mma16816(oc[2 * dp],     pa, b0, b1);
                mma16816(oc[2 * dp + 1], pa, b2, b3);
            }
        }

        if (t + 1 < NT && tid < BN) smask[1 - buf][tid] = mnext;
        CP_WAIT0();
        __syncthreads();
    }

    // ---- quad-reduce row sums, normalize, store ----
    lsum0 += __shfl_xor_sync(0xffffffffu, lsum0, 1);
    lsum0 += __shfl_xor_sync(0xffffffffu, lsum0, 2);
    lsum1 += __shfl_xor_sync(0xffffffffu, lsum1, 1);
    lsum1 += __shfl_xor_sync(0xffffffffu, lsum1, 2);
    float inv0 = (lsum0 > 0.0f) ? 1.0f / lsum0 : 0.0f;
    float inv1 = (lsum1 > 0.0f) ? 1.0f / lsum1 : 0.0f;

    const size_t row0 = (size_t)(b * NQL) + q0 + m0 + g;
#pragma unroll
    for (int dt = 0; dt < 8; ++dt) {
        int col = h * DH + 8 * dt + 2 * tig;
        *(float2*)(g_AO + row0 * HID + col) =
            make_float2(oc[dt][0] * inv0, oc[dt][1] * inv0);
        *(float2*)(g_AO + (row0 + 8) * HID + col) =
            make_float2(oc[dt][2] * inv1, oc[dt][3] * inv1);
    }
}

// ---------------------------------------------------------------------------
extern "C" void kernel_launch(void* const* d_in, const int* in_sizes, int n_in,
                              void* d_out, int out_size)
{
    const float* query     = (const float*)d_in[0];
    const float* key_value = (const float*)d_in[1];
    const int*   kv_mask   = (const int*)  d_in[2];
    const float* Wq = (const float*)d_in[3];
    const float* bq = (const float*)d_in[4];
    const float* Wk = (const float*)d_in[5];
    const float* bk = (const float*)d_in[6];
    const float* Wv = (const float*)d_in[7];
    const float* bv = (const float*)d_in[8];
    const float* Wo = (const float*)d_in[9];
    const float* bo = (const float*)d_in[10];

    void *Qp, *Kp, *Vp, *AOp;
    cudaGetSymbolAddress(&Qp,  g_Qh);
    cudaGetSymbolAddress(&Kp,  g_Kh);
    cudaGetSymbolAddress(&Vp,  g_Vh);
    cudaGetSymbolAddress(&AOp, g_AO);

    dim3 gblk(128);
    dim3 ggrid(HID / 64, MTOT / 64);   // (4, 128)

    hgemm_kernel<<<ggrid, gblk>>>(query,     Wq, bq, Qp, 0.125f, 1);  // Q pre-scaled
    hgemm_kernel<<<ggrid, gblk>>>(key_value, Wk, bk, Kp, 1.0f,   1);  // K
    hgemm_kernel<<<ggrid, gblk>>>(key_value, Wv, bv, Vp, 1.0f,   1);  // V

    attn_hmma_kernel<<<dim3(NQL / BM, BATCH * NH), 128>>>(kv_mask);

    hgemm_kernel<<<ggrid, gblk>>>((const float*)AOp, Wo, bo, d_out, 1.0f, 0);  // split, fp32 out
}

// round 10
// speedup vs baseline: 9.4783x; 1.0916x over previous
#include <cuda_runtime.h>
#include <cuda_fp16.h>
#include <math.h>
#include <stdint.h>

#define BATCH 2
#define NQL   4096
#define NKVL  4096
#define HID   256
#define NH    4
#define DH    64
#define MTOT  (BATCH * NQL)

// ---------------- scratch (device globals) ---------------------------------
__device__ __align__(16) __half g_Qh[BATCH * NH * NQL * DH];   // [bh][q][d], scaled by log2e/8
__device__ __align__(16) __half g_Kh[BATCH * NH * NKVL * DH];  // [bh][kv][d]
__device__ __align__(16) __half g_Vh[BATCH * NH * NKVL * DH];  // [bh][kv][d]
__device__ float g_AO[BATCH * NQL * HID];                      // attn out fp32

// ---------------- PTX helpers ----------------------------------------------
__device__ __forceinline__ uint32_t smem_u32(const void* p) {
    uint32_t a;
    asm("{ .reg .u64 t; cvta.to.shared.u64 t, %1; cvt.u32.u64 %0, t; }" : "=r"(a) : "l"(p));
    return a;
}
__device__ __forceinline__ void ldsm4(uint32_t& r0, uint32_t& r1, uint32_t& r2, uint32_t& r3, uint32_t a) {
    asm volatile("ldmatrix.sync.aligned.m8n8.x4.shared.b16 {%0,%1,%2,%3}, [%4];"
                 : "=r"(r0), "=r"(r1), "=r"(r2), "=r"(r3) : "r"(a));
}
__device__ __forceinline__ void ldsm4t(uint32_t& r0, uint32_t& r1, uint32_t& r2, uint32_t& r3, uint32_t a) {
    asm volatile("ldmatrix.sync.aligned.m8n8.x4.trans.shared.b16 {%0,%1,%2,%3}, [%4];"
                 : "=r"(r0), "=r"(r1), "=r"(r2), "=r"(r3) : "r"(a));
}
__device__ __forceinline__ void mma16816(float* c, const uint32_t* a, uint32_t b0, uint32_t b1) {
    asm volatile("mma.sync.aligned.m16n8k16.row.col.f32.f16.f16.f32 "
        "{%0,%1,%2,%3}, {%4,%5,%6,%7}, {%8,%9}, {%0,%1,%2,%3};"
        : "+f"(c[0]), "+f"(c[1]), "+f"(c[2]), "+f"(c[3])
        : "r"(a[0]), "r"(a[1]), "r"(a[2]), "r"(a[3]), "r"(b0), "r"(b1));
}
__device__ __forceinline__ uint32_t packh2(float x, float y) {
    __half2 h = __floats2half2_rn(x, y);
    return *(uint32_t*)&h;
}
__device__ __forceinline__ float ex2(float x) {
    float y;
    asm("ex2.approx.f32 %0, %1;" : "=f"(y) : "f"(x));
    return y;
}
#define CP16(dst, src)  asm volatile("cp.async.cg.shared.global [%0], [%1], 16;" :: "r"(dst), "l"(src))
#define CP_COMMIT()     asm volatile("cp.async.commit_group;" ::: "memory")
#define CP_WAIT0()      asm volatile("cp.async.wait_group 0;" ::: "memory")

#define LOG2E 1.4426950408889634f

// ---------------------------------------------------------------------------
// HMMA projection GEMM (single weight). mode 1: fp16 scatter to [bh][row][d].
// mode 0: Markidis split (hi*hi + lo*hi + hi*lo), fp32 row-major output.
// ---------------------------------------------------------------------------
#define GST 72

__device__ __forceinline__ void hgemm_pass(const __half* sA, const __half* sW,
                                           float c[8][4], int lane, int m0r)
{
    const int r   = (lane & 7) + ((lane >> 3) & 1) * 8;
    const int cq  = (lane >> 4) * 8;
    const int wr  = (lane & 7) + (((lane >> 3) & 1) << 3);
    const int wc  = (lane >> 4) << 3;

    uint32_t a[4][4];
#pragma unroll
    for (int kc = 0; kc < 4; ++kc) {
        uint32_t ad = smem_u32(sA + (m0r + r) * GST + kc * 16 + cq);
        ldsm4(a[kc][0], a[kc][1], a[kc][2], a[kc][3], ad);
    }
#pragma unroll
    for (int dp = 0; dp < 4; ++dp) {
#pragma unroll
        for (int kc = 0; kc < 4; ++kc) {
            uint32_t b0, b1, b2, b3;
            uint32_t ad = smem_u32(sW + (kc * 16 + wr) * GST + dp * 16 + wc);
            ldsm4t(b0, b1, b2, b3, ad);
            mma16816(c[2 * dp],     a[kc], b0, b1);
            mma16816(c[2 * dp + 1], a[kc], b2, b3);
        }
    }
}

__device__ __forceinline__ void stage_f16(const float* __restrict__ g, __half* s,
                                          int tid, int ld_f32, __half* slo, int want_lo)
{
#pragma unroll
    for (int l = 0; l < 4; ++l) {
        int idx = tid + 128 * l;
        int row = idx >> 3, cq = idx & 7;
        const float* ga = g + (size_t)row * ld_f32 + cq * 8;
        float4 x0 = *(const float4*)(ga);
        float4 x1 = *(const float4*)(ga + 4);
        __half2 h0 = __floats2half2_rn(x0.x, x0.y);
        __half2 h1 = __floats2half2_rn(x0.z, x0.w);
        __half2 h2 = __floats2half2_rn(x1.x, x1.y);
        __half2 h3 = __floats2half2_rn(x1.z, x1.w);
        *(uint4*)(s + row * GST + cq * 8) =
            make_uint4(*(uint32_t*)&h0, *(uint32_t*)&h1, *(uint32_t*)&h2, *(uint32_t*)&h3);
        if (want_lo) {
            __half2 l0 = __floats2half2_rn(x0.x - __low2float(h0),  x0.y - __high2float(h0));
            __half2 l1 = __floats2half2_rn(x0.z - __low2float(h1),  x0.w - __high2float(h1));
            __half2 l2 = __floats2half2_rn(x1.x - __low2float(h2),  x1.y - __high2float(h2));
            __half2 l3 = __floats2half2_rn(x1.z - __low2float(h3),  x1.w - __high2float(h3));
            *(uint4*)(slo + row * GST + cq * 8) =
                make_uint4(*(uint32_t*)&l0, *(uint32_t*)&l1, *(uint32_t*)&l2, *(uint32_t*)&l3);
        }
    }
}

__global__ __launch_bounds__(128) void hgemm_kernel(
    const float* __restrict__ A, const float* __restrict__ W,
    const float* __restrict__ bias, void* __restrict__ Cv,
    float alpha, int mode)
{
    __shared__ __half sA[64 * GST];
    __shared__ __half sW[64 * GST];
    __shared__ __half sAlo[64 * GST];
    __shared__ __half sWlo[64 * GST];

    const int tid  = threadIdx.x;
    const int warp = tid >> 5;
    const int lane = tid & 31;
    const int m0   = blockIdx.y * 64;
    const int n0   = blockIdx.x * 64;

    float c[8][4];
#pragma unroll
    for (int i = 0; i < 8; ++i)
#pragma unroll
        for (int j = 0; j < 4; ++j) c[i][j] = 0.0f;

    for (int k0 = 0; k0 < HID; k0 += 64) {
        stage_f16(A + (size_t)m0 * HID + k0, sA, tid, HID, sAlo, mode == 0);
        stage_f16(W + (size_t)k0 * HID + n0, sW, tid, HID, sWlo, mode == 0);
        __syncthreads();

        hgemm_pass(sA, sW, c, lane, warp * 16);
        if (mode == 0) {
            hgemm_pass(sAlo, sW, c, lane, warp * 16);
            hgemm_pass(sA, sWlo, c, lane, warp * 16);
        }
        __syncthreads();
    }

    const int g   = lane >> 2;
    const int tig = lane & 3;
    const int row0 = m0 + warp * 16 + g;
#pragma unroll
    for (int dt = 0; dt < 8; ++dt) {
        int col = 8 * dt + 2 * tig;
        float2 bv = *(const float2*)(bias + n0 + col);
        float v00 = (c[dt][0] + bv.x) * alpha;
        float v01 = (c[dt][1] + bv.y) * alpha;
        float v10 = (c[dt][2] + bv.x) * alpha;
        float v11 = (c[dt][3] + bv.y) * alpha;
        if (mode == 0) {
            float* C = (float*)Cv;
            *(float2*)(C + (size_t)row0 * HID + n0 + col)       = make_float2(v00, v01);
            *(float2*)(C + (size_t)(row0 + 8) * HID + n0 + col) = make_float2(v10, v11);
        } else {
            __half* C = (__half*)Cv;
            int h = n0 >> 6;
            {
                int b = row0 >> 12, rq = row0 & 4095;
                *(__half2*)(C + (((size_t)(b * NH + h) * NQL) + rq) * DH + col) =
                    __floats2half2_rn(v00, v01);
            }
            {
                int m1 = row0 + 8;
                int b = m1 >> 12, rq = m1 & 4095;
                *(__half2*)(C + (((size_t)(b * NH + h) * NQL) + rq) * DH + col) =
                    __floats2half2_rn(v10, v11);
            }
        }
    }
}

// ---------------------------------------------------------------------------
// Fused K+V projection: A staged/converted once, two weights, two outputs.
// ---------------------------------------------------------------------------
__global__ __launch_bounds__(128) void hgemm_kv_kernel(
    const float* __restrict__ A,
    const float* __restrict__ Wk, const float* __restrict__ bk,
    const float* __restrict__ Wv, const float* __restrict__ bv)
{
    __shared__ __half sA[64 * GST];
    __shared__ __half sWk[64 * GST];
    __shared__ __half sWv[64 * GST];

    const int tid  = threadIdx.x;
    const int warp = tid >> 5;
    const int lane = tid & 31;
    const int m0   = blockIdx.y * 64;
    const int n0   = blockIdx.x * 64;

    float ck[8][4], cv[8][4];
#pragma unroll
    for (int i = 0; i < 8; ++i)
#pragma unroll
        for (int j = 0; j < 4; ++j) { ck[i][j] = 0.0f; cv[i][j] = 0.0f; }

    for (int k0 = 0; k0 < HID; k0 += 64) {
        stage_f16(A  + (size_t)m0 * HID + k0, sA,  tid, HID, 0, 0);
        stage_f16(Wk + (size_t)k0 * HID + n0, sWk, tid, HID, 0, 0);
        stage_f16(Wv + (size_t)k0 * HID + n0, sWv, tid, HID, 0, 0);
        __syncthreads();
        hgemm_pass(sA, sWk, ck, lane, warp * 16);
        hgemm_pass(sA, sWv, cv, lane, warp * 16);
        __syncthreads();
    }

    const int g   = lane >> 2;
    const int tig = lane & 3;
    const int row0 = m0 + warp * 16 + g;
    const int h = n0 >> 6;
#pragma unroll
    for (int dt = 0; dt < 8; ++dt) {
        int col = 8 * dt + 2 * tig;
        float2 bkv = *(const float2*)(bk + n0 + col);
        float2 bvv = *(const float2*)(bv + n0 + col);
        int b0i = row0 >> 12, rq0 = row0 & 4095;
        int m1 = row0 + 8;
        int b1i = m1 >> 12, rq1 = m1 & 4095;
        size_t o0 = (((size_t)(b0i * NH + h) * NKVL) + rq0) * DH + col;
        size_t o1 = (((size_t)(b1i * NH + h) * NKVL) + rq1) * DH + col;
        *(__half2*)(g_Kh + o0) = __floats2half2_rn(ck[dt][0] + bkv.x, ck[dt][1] + bkv.y);
        *(__half2*)(g_Kh + o1) = __floats2half2_rn(ck[dt][2] + bkv.x, ck[dt][3] + bkv.y);
        *(__half2*)(g_Vh + o0) = __floats2half2_rn(cv[dt][0] + bvv.x, cv[dt][1] + bvv.y);
        *(__half2*)(g_Vh + o1) = __floats2half2_rn(cv[dt][2] + bvv.x, cv[dt][3] + bvv.y);
    }
}

// ---------------------------------------------------------------------------
// HMMA flash attention, base-2 softmax (Q pre-scaled by log2e/8).
// CTA = 128 q rows, 4 warps, 32 rows (two m16 tiles) per warp. Each K/V
// ldmatrix feeds 4 MMAs -> halved LDS traffic vs m16-per-warp.
// ---------------------------------------------------------------------------
#define BM 128
#define BN 64
#define KST 72

__global__ __launch_bounds__(128, 3) void attn_hmma_kernel(const int* __restrict__ kv_mask)
{
    extern __shared__ __half smem_dyn[];
    __half* sQ    = smem_dyn;                 // [128][KST]
    __half* sK0   = sQ + BM * KST;            // [64][KST] x2
    __half* sV0   = sK0 + 2 * BN * KST;       // [64][KST] x2
    float*  smask = (float*)(sV0 + 2 * BN * KST);  // [2][64]

    const int tid  = threadIdx.x;
    const int warp = tid >> 5;
    const int lane = tid & 31;
    const int g    = lane >> 2;
    const int tig  = lane & 3;
    const int q0   = blockIdx.x * BM;
    const int bh   = blockIdx.y;
    const int b    = bh >> 2, h = bh & 3;
    const int m0   = warp * 32;

    const __half* Qg = g_Qh + ((size_t)bh * NQL + q0) * DH;
    const __half* Kg = g_Kh + (size_t)bh * NKVL * DH;
    const __half* Vg = g_Vh + (size_t)bh * NKVL * DH;
    const int*    Mg = kv_mask + b * NKVL;

    // ---- prologue: Q direct (1024 chunks), KV tile 0 async (512 each) ----
#pragma unroll
    for (int l = 0; l < 8; ++l) {
        int idx = tid + 128 * l;
        int row = idx >> 3, c = idx & 7;
        *(uint4*)(sQ + row * KST + c * 8) = *(const uint4*)(Qg + (size_t)row * DH + c * 8);
    }
#pragma unroll
    for (int l = 0; l < 4; ++l) {
        int idx = tid + 128 * l;
        int row = idx >> 3, c = idx & 7;
        CP16(smem_u32(sK0 + row * KST + c * 8), (const void*)(Kg + (size_t)row * DH + c * 8));
        CP16(smem_u32(sV0 + row * KST + c * 8), (const void*)(Vg + (size_t)row * DH + c * 8));
    }
    CP_COMMIT();
    if (tid < BN) smask[tid] = Mg[tid] ? 1.0f : 0.0f;
    CP_WAIT0();
    __syncthreads();

    // ---- Q fragments for both m-tiles (held in regs) ----
    uint32_t qa[2][4][4];
    {
        int r = (lane & 7) + ((lane >> 3) & 1) * 8;
        int cq = (lane >> 4) * 8;
#pragma unroll
        for (int mt = 0; mt < 2; ++mt)
#pragma unroll
            for (int kc = 0; kc < 4; ++kc) {
                uint32_t a = smem_u32(sQ + (m0 + mt * 16 + r) * KST + kc * 16 + cq);
                ldsm4(qa[mt][kc][0], qa[mt][kc][1], qa[mt][kc][2], qa[mt][kc][3], a);
            }
    }

    float oc[2][8][4];
#pragma unroll
    for (int mt = 0; mt < 2; ++mt)
#pragma unroll
        for (int i = 0; i < 8; ++i)
#pragma unroll
            for (int j = 0; j < 4; ++j) oc[mt][i][j] = 0.0f;
    float lsum[2][2] = {{0.0f, 0.0f}, {0.0f, 0.0f}};

    const int krow = (lane & 7) + ((lane >> 4) << 3);
    const int kcol = ((lane >> 3) & 1) << 3;
    const int vrow = (lane & 7) + (((lane >> 3) & 1) << 3);
    const int vcol = (lane >> 4) << 3;

    const int NT = NKVL / BN;   // 64

    for (int t = 0; t < NT; ++t) {
        const int buf = t & 1;
        const __half* s_k = sK0 + buf * BN * KST;
        const __half* s_v = sV0 + buf * BN * KST;
        const float*  s_m = smask + buf * BN;

        float mnext = 1.0f;
        if (t + 1 < NT) {
            const __half* Kn = Kg + (size_t)(t + 1) * BN * DH;
            const __half* Vn = Vg + (size_t)(t + 1) * BN * DH;
            __half* dK = sK0 + (1 - buf) * BN * KST;
            __half* dV = sV0 + (1 - buf) * BN * KST;
#pragma unroll
            for (int l = 0; l < 4; ++l) {
                int idx = tid + 128 * l;
                int row = idx >> 3, c = idx & 7;
                CP16(smem_u32(dK + row * KST + c * 8), (const void*)(Kn + (size_t)row * DH + c * 8));
                CP16(smem_u32(dV + row * KST + c * 8), (const void*)(Vn + (size_t)row * DH + c * 8));
            }
            CP_COMMIT();
            if (tid < BN) mnext = Mg[(t + 1) * BN + tid] ? 1.0f : 0.0f;
        }

#pragma unroll
        for (int np = 0; np < 4; ++np) {
            const int n0 = 16 * np;
            float s[2][2][4];
#pragma unroll
            for (int mt = 0; mt < 2; ++mt)
#pragma unroll
                for (int nt = 0; nt < 2; ++nt)
#pragma unroll
                    for (int j = 0; j < 4; ++j) s[mt][nt][j] = 0.0f;

#pragma unroll
            for (int kc = 0; kc < 4; ++kc) {
                uint32_t b0, b1, b2, b3;
                uint32_t a = smem_u32(s_k + (n0 + krow) * KST + kc * 16 + kcol);
                ldsm4(b0, b1, b2, b3, a);
                mma16816(s[0][0], qa[0][kc], b0, b1);
                mma16816(s[0][1], qa[0][kc], b2, b3);
                mma16816(s[1][0], qa[1][kc], b0, b1);
                mma16816(s[1][1], qa[1][kc], b2, b3);
            }

            float mA0 = s_m[n0 + 2 * tig];
            float mA1 = s_m[n0 + 2 * tig + 1];
            float mB0 = s_m[n0 + 8 + 2 * tig];
            float mB1 = s_m[n0 + 8 + 2 * tig + 1];

            uint32_t pa[2][4];
#pragma unroll
            for (int mt = 0; mt < 2; ++mt) {
                float p00 = ex2(s[mt][0][0]) * mA0, p01 = ex2(s[mt][0][1]) * mA1;
                float p02 = ex2(s[mt][0][2]) * mA0, p03 = ex2(s[mt][0][3]) * mA1;
                float p10 = ex2(s[mt][1][0]) * mB0, p11 = ex2(s[mt][1][1]) * mB1;
                float p12 = ex2(s[mt][1][2]) * mB0, p13 = ex2(s[mt][1][3]) * mB1;
                lsum[mt][0] += (p00 + p01) + (p10 + p11);
                lsum[mt][1] += (p02 + p03) + (p12 + p13);
                pa[mt][0] = packh2(p00, p01);
                pa[mt][1] = packh2(p02, p03);
                pa[mt][2] = packh2(p10, p11);
                pa[mt][3] = packh2(p12, p13);
            }

#pragma unroll
            for (int dp = 0; dp < 4; ++dp) {
                uint32_t b0, b1, b2, b3;
                uint32_t a = smem_u32(s_v + (n0 + vrow) * KST + dp * 16 + vcol);
                ldsm4t(b0, b1, b2, b3, a);
                mma16816(oc[0][2 * dp],     pa[0], b0, b1);
                mma16816(oc[0][2 * dp + 1], pa[0], b2, b3);
                mma16816(oc[1][2 * dp],     pa[1], b0, b1);
                mma16816(oc[1][2 * dp + 1], pa[1], b2, b3);
            }
        }

        if (t + 1 < NT && tid < BN) smask[(1 - buf) * BN + tid] = mnext;
        CP_WAIT0();
        __syncthreads();
    }

    // ---- quad-reduce row sums, normalize, store ----
#pragma unroll
    for (int mt = 0; mt < 2; ++mt) {
#pragma unroll
        for (int hh = 0; hh < 2; ++hh) {
            lsum[mt][hh] += __shfl_xor_sync(0xffffffffu, lsum[mt][hh], 1);
            lsum[mt][hh] += __shfl_xor_sync(0xffffffffu, lsum[mt][hh], 2);
        }
        float inv0 = (lsum[mt][0] > 0.0f) ? 1.0f / lsum[mt][0] : 0.0f;
        float inv1 = (lsum[mt][1] > 0.0f) ? 1.0f / lsum[mt][1] : 0.0f;
        const size_t row0 = (size_t)(b * NQL) + q0 + m0 + mt * 16 + g;
#pragma unroll
        for (int dt = 0; dt < 8; ++dt) {
            int col = h * DH + 8 * dt + 2 * tig;
            *(float2*)(g_AO + row0 * HID + col) =
                make_float2(oc[mt][dt][0] * inv0, oc[mt][dt][1] * inv0);
            *(float2*)(g_AO + (row0 + 8) * HID + col) =
                make_float2(oc[mt][dt][2] * inv1, oc[mt][dt][3] * inv1);
        }
    }
}

// ---------------------------------------------------------------------------
extern "C" void kernel_launch(void* const* d_in, const int* in_sizes, int n_in,
                              void* d_out, int out_size)
{
    const float* query     = (const float*)d_in[0];
    const float* key_value = (const float*)d_in[1];
    const int*   kv_mask   = (const int*)  d_in[2];
    const float* Wq = (const float*)d_in[3];
    const float* bq = (const float*)d_in[4];
    const float* Wk = (const float*)d_in[5];
    const float* bk = (const float*)d_in[6];
    const float* Wv = (const float*)d_in[7];
    const float* bv = (const float*)d_in[8];
    const float* Wo = (const float*)d_in[9];
    const float* bo = (const float*)d_in[10];

    void *Qp, *AOp;
    cudaGetSymbolAddress(&Qp,  g_Qh);
    cudaGetSymbolAddress(&AOp, g_AO);

    dim3 gblk(128);
    dim3 ggrid(HID / 64, MTOT / 64);   // (4, 128)

    // Q pre-scaled by log2e / sqrt(DH) for base-2 softmax
    hgemm_kernel<<<ggrid, gblk>>>(query, Wq, bq, Qp, 0.125f * LOG2E, 1);
    hgemm_kv_kernel<<<ggrid, gblk>>>(key_value, Wk, bk, Wv, bv);

    const int attn_smem = (BM * KST + 4 * BN * KST) * 2 + 2 * BN * 4;  // 55808 B
    cudaFuncSetAttribute(attn_hmma_kernel, cudaFuncAttributeMaxDynamicSharedMemorySize, attn_smem);
    attn_hmma_kernel<<<dim3(NQL / BM, BATCH * NH), 128, attn_smem>>>(kv_mask);

    hgemm_kernel<<<ggrid, gblk>>>((const float*)AOp, Wo, bo, d_out, 1.0f, 0);  // split, fp32 out
}